// round 2
// baseline (speedup 1.0000x reference)
#include <cuda_runtime.h>
#include <cstdint>

// Problem constants
constexpr int T = 512, B = 64, F = 32, K = 32;

constexpr int OFF_SCORE = 0;
constexpr int OFF_MAXS  = 64;                    // [T,B,K] floats
constexpr int OFF_IDX   = 64 + T * B * K;       // [T,B,K] (ints as float)
constexpr int OFF_FEATS = 64 + 2 * T * B * K;   // [T,B,K] floats

#define FULL 0xffffffffu

__device__ __forceinline__ float ex2f(float x) {
    float y; asm("ex2.approx.f32 %0, %1;" : "=f"(y) : "f"(x)); return y;
}
__device__ __forceinline__ float lg2f(float x) {
    float y; asm("lg2.approx.f32 %0, %1;" : "=f"(y) : "f"(x)); return y;
}

constexpr float L2E = 1.4426950408889634f;
constexpr float LN2 = 0.6931471805599453f;

// ---------------------------------------------------------------------------
// Kernel 1: emission feats.  One warp per (t,b); lane = tag k.
// feats[t,b,k] = sum_f W[ idx ],  idx = (t<len[b]) ? words[t,b,f]+k : 0
// Also writes max_s[0] = feats[0] and max_s_idx[0] = 0.
// ---------------------------------------------------------------------------
__global__ void feats_kernel(const int* __restrict__ words,
                             const int* __restrict__ lens,
                             const float* __restrict__ W,
                             float* __restrict__ out) {
    int gw   = (blockIdx.x * blockDim.x + threadIdx.x) >> 5;   // t*B + b
    int lane = threadIdx.x & 31;
    if (gw >= T * B) return;
    int t = gw >> 6;     // / B (B==64)
    int b = gw & 63;

    int L = __ldg(&lens[b]);
    bool valid = (t < L);

    // coalesced: lane f loads word f of this (t,b)
    int w = valid ? __ldg(&words[gw * F + lane]) : 0;

    float s0 = 0.f, s1 = 0.f, s2 = 0.f, s3 = 0.f;
#pragma unroll
    for (int f = 0; f < F; f += 4) {
        int w0 = __shfl_sync(FULL, w, f);
        int w1 = __shfl_sync(FULL, w, f + 1);
        int w2 = __shfl_sync(FULL, w, f + 2);
        int w3 = __shfl_sync(FULL, w, f + 3);
        // index zeroing happens AFTER adding the tag offset in the reference
        int i0 = valid ? (w0 + lane) : 0;
        int i1 = valid ? (w1 + lane) : 0;
        int i2 = valid ? (w2 + lane) : 0;
        int i3 = valid ? (w3 + lane) : 0;
        s0 += __ldg(&W[i0]);
        s1 += __ldg(&W[i1]);
        s2 += __ldg(&W[i2]);
        s3 += __ldg(&W[i3]);
    }
    float s = (s0 + s1) + (s2 + s3);

    out[OFF_FEATS + gw * K + lane] = s;
    if (t == 0) {
        out[OFF_MAXS + b * K + lane] = s;     // max_s[0] = feats[0]
        out[OFF_IDX  + b * K + lane] = 0.f;   // max_s_idx[0] = 0
    }
}

// ---------------------------------------------------------------------------
// Kernel 2: serial recurrence.  One block per batch b, 2 warps:
//   warp 0: forward algorithm (logsumexp) -> forward_score[b]
//   warp 1: Viterbi max recursion -> max_s[t] for t=1..T-1
// lane = current tag k; tc[j] = trans[j][k] held in registers.
// ---------------------------------------------------------------------------
__global__ void __launch_bounds__(64, 1)
rec_kernel(const float* __restrict__ trans,
           const int* __restrict__ lens,
           float* __restrict__ out) {
    int b    = blockIdx.x;
    int wid  = threadIdx.x >> 5;
    int lane = threadIdx.x & 31;
    const float* feats = out + OFF_FEATS;
    float* maxs = out + OFF_MAXS;

    int L = __ldg(&lens[b]);

    float tc[K];
#pragma unroll
    for (int j = 0; j < K; j++) tc[j] = __ldg(&trans[j * K + lane]);

    float f0 = feats[b * K + lane];

    if (wid == 0) {
        // ------------------- forward (logsumexp) chain -------------------
        float et[K];
#pragma unroll
        for (int j = 0; j < K; j++) et[j] = ex2f(tc[j] * L2E);   // exp(trans)

        float alpha = f0;
        float fA = feats[(1 * B + b) * K + lane];
        float fB = feats[(2 * B + b) * K + lane];

        for (int t = 1; t < T; t++) {
            float f = fA;
            fA = fB;
            fB = (t + 2 < T) ? feats[((t + 2) * B + b) * K + lane] : 0.f;

            float C = __shfl_sync(FULL, alpha, 0);        // any near-max works
            float E = ex2f((alpha - C) * L2E);            // exp(alpha_j - C)

            float s0 = 0.f, s1 = 0.f, s2 = 0.f, s3 = 0.f;
#pragma unroll
            for (int j = 0; j < K; j += 4) {
                s0 = fmaf(__shfl_sync(FULL, E, j),     et[j],     s0);
                s1 = fmaf(__shfl_sync(FULL, E, j + 1), et[j + 1], s1);
                s2 = fmaf(__shfl_sync(FULL, E, j + 2), et[j + 2], s2);
                s3 = fmaf(__shfl_sync(FULL, E, j + 3), et[j + 3], s3);
            }
            float s = (s0 + s1) + (s2 + s3);
            float anew = C + lg2f(s) * LN2 + f;
            if (t < L) alpha = anew;                      // freeze on pad
        }

        // final logsumexp over tags
        float m = alpha;
#pragma unroll
        for (int o = 16; o; o >>= 1) m = fmaxf(m, __shfl_xor_sync(FULL, m, o));
        float e = ex2f((alpha - m) * L2E);
#pragma unroll
        for (int o = 16; o; o >>= 1) e += __shfl_xor_sync(FULL, e, o);
        if (lane == 0) out[OFF_SCORE + b] = m + lg2f(e) * LN2;

    } else {
        // ------------------- Viterbi (max) chain -------------------
        const float NEG_INF = __int_as_float(0xff800000);
        float delta = f0;
        float fA = feats[(1 * B + b) * K + lane];
        float fB = feats[(2 * B + b) * K + lane];

        for (int t = 1; t < T; t++) {
            float f = fA;
            fA = fB;
            fB = (t + 2 < T) ? feats[((t + 2) * B + b) * K + lane] : 0.f;

            float m0 = NEG_INF, m1 = NEG_INF, m2 = NEG_INF, m3 = NEG_INF;
#pragma unroll
            for (int j = 0; j < K; j += 4) {
                m0 = fmaxf(m0, __shfl_sync(FULL, delta, j)     + tc[j]);
                m1 = fmaxf(m1, __shfl_sync(FULL, delta, j + 1) + tc[j + 1]);
                m2 = fmaxf(m2, __shfl_sync(FULL, delta, j + 2) + tc[j + 2]);
                m3 = fmaxf(m3, __shfl_sync(FULL, delta, j + 3) + tc[j + 3]);
            }
            float dnew = fmaxf(fmaxf(m0, m1), fmaxf(m2, m3)) + f;
            if (t < L) delta = dnew;                      // freeze on pad
            maxs[(t * B + b) * K + lane] = delta;         // post-where value
        }
    }
}

// ---------------------------------------------------------------------------
// Kernel 3: backpointers (parallel).  Warp per (t,b), t in [1,T); lane = k.
// bp[t,b,k] = argmax_j ( max_s[t-1,b,j] + trans[j,k] )   (first index on ties)
// ---------------------------------------------------------------------------
__global__ void bp_kernel(const float* __restrict__ trans,
                          float* __restrict__ out) {
    int gw   = (blockIdx.x * blockDim.x + threadIdx.x) >> 5;
    int lane = threadIdx.x & 31;
    if (gw >= (T - 1) * B) return;
    int t = gw / B + 1;
    int b = gw % B;

    const float* maxs = out + OFF_MAXS;

    float tcj[K];
#pragma unroll
    for (int j = 0; j < K; j++) tcj[j] = __ldg(&trans[j * K + lane]);

    float dprev = maxs[((t - 1) * B + b) * K + lane];   // lane acts as j source

    float best = __shfl_sync(FULL, dprev, 0) + tcj[0];
    int   bi   = 0;
#pragma unroll
    for (int j = 1; j < K; j++) {
        float sc = __shfl_sync(FULL, dprev, j) + tcj[j];
        if (sc > best) { best = sc; bi = j; }           // strict > keeps first
    }
    out[OFF_IDX + (t * B + b) * K + lane] = (float)bi;
}

// ---------------------------------------------------------------------------
extern "C" void kernel_launch(void* const* d_in, const int* in_sizes, int n_in,
                              void* d_out, int out_size) {
    const int*   words = (const int*)d_in[0];     // [T,B,F] int32
    const int*   lens  = (const int*)d_in[1];     // [B] int32
    const float* W     = (const float*)d_in[2];   // [1e6] f32
    const float* trans = (const float*)d_in[3];   // [K,K] f32
    float* out = (float*)d_out;

    feats_kernel<<<(T * B) / 8, 256>>>(words, lens, W, out);
    rec_kernel<<<B, 64>>>(trans, lens, out);
    bp_kernel<<<((T - 1) * B + 7) / 8, 256>>>(trans, out);
}